// round 7
// baseline (speedup 1.0000x reference)
#include <cuda_runtime.h>
#include <math.h>

#define Dq 256
#define Mq 512
#define RB 32
#define NT 512
#define NROWS (32*4096)

// SMEM float offsets
#define XS_OFF   0                        // xsT [256][32]  k-major
#define WS_OFF   (XS_OFF + Dq*RB)         // wsT [512][36]  logits/weights (group0 partial)
#define MS_OFF   (WS_OFF + Mq*36)         // msT [256][36]  memory_read
#define PS_OFF   (MS_OFF + Dq*36)         // PS  [512][36]  partial-sum scratch
#define R1_OFF   (PS_OFF + Mq*36)
#define R2_OFF   (R1_OFF + 512)
#define SMEM_FLOATS (R2_OFF + 512)        // 55296 floats = 216 KB

__device__ float g_memT[Dq*Mq];   // [k][m]  = memory[m][k]
__device__ float g_WgT[2*Dq*Dq];  // [dc][e] = Wg[e][dc]

typedef unsigned long long u64;

__device__ __forceinline__ u64 bcast2(float v){
    u64 r; asm("mov.b64 %0, {%1, %1};" : "=l"(r) : "f"(v)); return r;
}
__device__ __forceinline__ void unpack2(u64 v, float& lo, float& hi){
    asm("mov.b64 {%0, %1}, %2;" : "=f"(lo), "=f"(hi) : "l"(v));
}
__device__ __forceinline__ void ffma2(u64& d, u64 a, u64 b){
    asm("fma.rn.f32x2 %0, %1, %2, %0;" : "+l"(d) : "l"(a), "l"(b));
}
__device__ __forceinline__ float sigmoidf_(float p){
    return 1.f/(1.f+__expf(-p));
}

__global__ void vm_prep(const float* __restrict__ mem, const float* __restrict__ wg){
    int idx = blockIdx.x*blockDim.x + threadIdx.x;
    if (idx < Mq*Dq){
        int m = idx >> 8, k = idx & 255;      // memory: [512][256]
        g_memT[k*Mq + m] = mem[idx];
        int e = idx >> 9, dc = idx & 511;     // Wg: [256][512]
        g_WgT[dc*Dq + e] = wg[idx];
    }
}

__global__ __launch_bounds__(NT, 1)
void vm_fused(const float* __restrict__ x,
              const float* __restrict__ memv,
              const float* __restrict__ bg,
              float* __restrict__ out_enh,
              float* __restrict__ out_w)
{
    extern __shared__ float smem[];
    float* xsT  = smem + XS_OFF;   // [k][32]
    float* wsT  = smem + WS_OFF;   // [k][36]
    float* msT  = smem + MS_OFF;   // [k][36]
    float* PS   = smem + PS_OFF;   // [k][36]
    float* red1 = smem + R1_OFF;
    float* red2 = smem + R2_OFF;

    const int tid = threadIdx.x;
    const int rowbase = blockIdx.x * RB;
    const int wid = tid >> 5, lane = tid & 31;

    const int kh = wid >> 3;           // 0/1 : k-split group
    const int wc = wid & 7;            // col-block within group
    const int row_g = lane >> 3;       // 0..3
    const int col_o = lane & 7;        // 0..7
    const int r0 = row_g * 8;          // 8 rows per lane

    // ---------------- Phase A: x block -> xsT[k][r] (k-major) --------------
    {
        int r = lane;
        #pragma unroll
        for (int cc = 0; cc < 4; cc++){
            int c4 = wid + cc*16;
            float4 v = *(const float4*)(x + (size_t)(rowbase + r)*Dq + c4*4);
            xsT[(c4*4+0)*RB + r] = v.x;
            xsT[(c4*4+1)*RB + r] = v.y;
            xsT[(c4*4+2)*RB + r] = v.z;
            xsT[(c4*4+3)*RB + r] = v.w;
        }
    }
    __syncthreads();

    // ---------------- Phase B: logits = x @ memory^T  (k-split) ------------
    // group kh handles k in [kh*128, kh*128+128). warp: 32 rows x 64 cols.
    // lane: 8 rows x 8 cols (two 4-col strips). group0 -> wsT, group1 -> PS.
    {
        const int c0 = wc*64 + col_o*4;
        const int c1 = c0 + 32;
        const int kb = kh * 128;
        u64 acc[8][4];
        #pragma unroll
        for (int i=0;i<8;i++){ acc[i][0]=0; acc[i][1]=0; acc[i][2]=0; acc[i][3]=0; }

        #pragma unroll 4
        for (int k=0;k<128;k++){
            const int kk = kb + k;
            float4 av0 = *(const float4*)(xsT + kk*RB + r0);
            float4 av1 = *(const float4*)(xsT + kk*RB + r0 + 4);
            ulonglong2 B0 = *(const ulonglong2*)(g_memT + kk*Mq + c0);
            ulonglong2 B1 = *(const ulonglong2*)(g_memT + kk*Mq + c1);
            u64 a;
            a = bcast2(av0.x); ffma2(acc[0][0],a,B0.x); ffma2(acc[0][1],a,B0.y); ffma2(acc[0][2],a,B1.x); ffma2(acc[0][3],a,B1.y);
            a = bcast2(av0.y); ffma2(acc[1][0],a,B0.x); ffma2(acc[1][1],a,B0.y); ffma2(acc[1][2],a,B1.x); ffma2(acc[1][3],a,B1.y);
            a = bcast2(av0.z); ffma2(acc[2][0],a,B0.x); ffma2(acc[2][1],a,B0.y); ffma2(acc[2][2],a,B1.x); ffma2(acc[2][3],a,B1.y);
            a = bcast2(av0.w); ffma2(acc[3][0],a,B0.x); ffma2(acc[3][1],a,B0.y); ffma2(acc[3][2],a,B1.x); ffma2(acc[3][3],a,B1.y);
            a = bcast2(av1.x); ffma2(acc[4][0],a,B0.x); ffma2(acc[4][1],a,B0.y); ffma2(acc[4][2],a,B1.x); ffma2(acc[4][3],a,B1.y);
            a = bcast2(av1.y); ffma2(acc[5][0],a,B0.x); ffma2(acc[5][1],a,B0.y); ffma2(acc[5][2],a,B1.x); ffma2(acc[5][3],a,B1.y);
            a = bcast2(av1.z); ffma2(acc[6][0],a,B0.x); ffma2(acc[6][1],a,B0.y); ffma2(acc[6][2],a,B1.x); ffma2(acc[6][3],a,B1.y);
            a = bcast2(av1.w); ffma2(acc[7][0],a,B0.x); ffma2(acc[7][1],a,B0.y); ffma2(acc[7][2],a,B1.x); ffma2(acc[7][3],a,B1.y);
        }

        float* dst = (kh == 0) ? wsT : PS;
        #pragma unroll
        for (int half=0; half<2; half++){
            float t[4][8];
            #pragma unroll
            for (int i=0;i<4;i++){
                int ii = half*4 + i;
                unpack2(acc[ii][0], t[i][0], t[i][1]);
                unpack2(acc[ii][1], t[i][2], t[i][3]);
                unpack2(acc[ii][2], t[i][4], t[i][5]);
                unpack2(acc[ii][3], t[i][6], t[i][7]);
            }
            #pragma unroll
            for (int cc=0; cc<8; cc++){
                int col = (cc<4) ? (c0+cc) : (c1+cc-4);
                float4 v; v.x=t[0][cc]; v.y=t[1][cc]; v.z=t[2][cc]; v.w=t[3][cc];
                *(float4*)(dst + col*36 + r0 + half*4) = v;
            }
        }
    }
    __syncthreads();

    // ---------------- Phase C: reduce partials + softmax -------------------
    // warp w owns k-block [w*32, w*32+32); lane = row.
    {
        const int k0 = wid*32;
        float v[32];
        float mx = -3.402823466e38f;
        #pragma unroll
        for (int j=0;j<32;j++){
            v[j] = wsT[(k0+j)*36 + lane] + PS[(k0+j)*36 + lane];
            mx = fmaxf(mx, v[j]);
        }
        red1[wid*32 + lane] = mx;
        __syncthreads();
        float rm = -3.402823466e38f;
        #pragma unroll
        for (int i=0;i<16;i++) rm = fmaxf(rm, red1[i*32 + lane]);
        float sm = 0.f;
        #pragma unroll
        for (int j=0;j<32;j++){ v[j] = __expf(v[j]-rm); sm += v[j]; }
        red2[wid*32 + lane] = sm;
        __syncthreads();
        float rs = 0.f;
        #pragma unroll
        for (int i=0;i<16;i++) rs += red2[i*32 + lane];
        float inv = 1.f / rs;
        #pragma unroll
        for (int j=0;j<32;j++) wsT[(k0+j)*36 + lane] = v[j]*inv;
        __syncthreads();
        // coalesced out_w writeout (warp = 2 rows)
        #pragma unroll
        for (int rr=0; rr<2; rr++){
            int r = wid*2 + rr;
            float* wout = out_w + (size_t)(rowbase + r)*Mq;
            #pragma unroll
            for (int t=0;t<16;t++)
                wout[lane + 32*t] = wsT[(lane + 32*t)*36 + r];
        }
    }

    // ---------------- Phase D: mr = w @ memory  (k-split, K=512) -----------
    // group kh: k in [kh*256, +256). warp: 32 rows x 32 cols, lane 8x4.
    {
        const int c0 = wc*32 + col_o*4;
        const int kb = kh * 256;
        u64 acc[8][2];
        #pragma unroll
        for (int i=0;i<8;i++){ acc[i][0]=0; acc[i][1]=0; }
        #pragma unroll 4
        for (int k=0;k<256;k++){
            const int kk = kb + k;
            float4 av0 = *(const float4*)(wsT + kk*36 + r0);
            float4 av1 = *(const float4*)(wsT + kk*36 + r0 + 4);
            ulonglong2 Bv = *(const ulonglong2*)(memv + kk*Dq + c0);
            u64 a;
            a = bcast2(av0.x); ffma2(acc[0][0],a,Bv.x); ffma2(acc[0][1],a,Bv.y);
            a = bcast2(av0.y); ffma2(acc[1][0],a,Bv.x); ffma2(acc[1][1],a,Bv.y);
            a = bcast2(av0.z); ffma2(acc[2][0],a,Bv.x); ffma2(acc[2][1],a,Bv.y);
            a = bcast2(av0.w); ffma2(acc[3][0],a,Bv.x); ffma2(acc[3][1],a,Bv.y);
            a = bcast2(av1.x); ffma2(acc[4][0],a,Bv.x); ffma2(acc[4][1],a,Bv.y);
            a = bcast2(av1.y); ffma2(acc[5][0],a,Bv.x); ffma2(acc[5][1],a,Bv.y);
            a = bcast2(av1.z); ffma2(acc[6][0],a,Bv.x); ffma2(acc[6][1],a,Bv.y);
            a = bcast2(av1.w); ffma2(acc[7][0],a,Bv.x); ffma2(acc[7][1],a,Bv.y);
        }
        float* dst = (kh == 0) ? msT : PS;
        #pragma unroll
        for (int half=0; half<2; half++){
            float t[4][4];
            #pragma unroll
            for (int i=0;i<4;i++){
                int ii = half*4 + i;
                unpack2(acc[ii][0], t[i][0], t[i][1]);
                unpack2(acc[ii][1], t[i][2], t[i][3]);
            }
            #pragma unroll
            for (int cc=0; cc<4; cc++){
                float4 v; v.x=t[0][cc]; v.y=t[1][cc]; v.z=t[2][cc]; v.w=t[3][cc];
                *(float4*)(msT == dst ? (msT + (c0+cc)*36 + r0 + half*4)
                                      : (PS  + (c0+cc)*36 + r0 + half*4)) = v;
            }
        }
    }
    __syncthreads();
    // reduce PS into msT: 256 cols x 32 rows
    {
        #pragma unroll
        for (int t=0;t<16;t++){
            int idx = tid + t*512;          // 0..8191
            int col = idx >> 5, row = idx & 31;
            msT[col*36 + row] += PS[col*36 + row];
        }
    }
    __syncthreads();

    // ---------------- Phase E: gate GEMMs (group0: W1.x, group1: W2.mr) ----
    {
        const int e0 = wc*32 + col_o*4;
        u64 acc[8][2];
        #pragma unroll
        for (int i=0;i<8;i++){ acc[i][0]=0; acc[i][1]=0; }

        if (kh == 0){
            #pragma unroll 4
            for (int k=0;k<256;k++){
                float4 av0 = *(const float4*)(xsT + k*RB + r0);
                float4 av1 = *(const float4*)(xsT + k*RB + r0 + 4);
                ulonglong2 Bv = *(const ulonglong2*)(g_WgT + (size_t)k*Dq + e0);
                u64 a;
                a = bcast2(av0.x); ffma2(acc[0][0],a,Bv.x); ffma2(acc[0][1],a,Bv.y);
                a = bcast2(av0.y); ffma2(acc[1][0],a,Bv.x); ffma2(acc[1][1],a,Bv.y);
                a = bcast2(av0.z); ffma2(acc[2][0],a,Bv.x); ffma2(acc[2][1],a,Bv.y);
                a = bcast2(av0.w); ffma2(acc[3][0],a,Bv.x); ffma2(acc[3][1],a,Bv.y);
                a = bcast2(av1.x); ffma2(acc[4][0],a,Bv.x); ffma2(acc[4][1],a,Bv.y);
                a = bcast2(av1.y); ffma2(acc[5][0],a,Bv.x); ffma2(acc[5][1],a,Bv.y);
                a = bcast2(av1.z); ffma2(acc[6][0],a,Bv.x); ffma2(acc[6][1],a,Bv.y);
                a = bcast2(av1.w); ffma2(acc[7][0],a,Bv.x); ffma2(acc[7][1],a,Bv.y);
            }
            // store partial z1 to PS
            #pragma unroll
            for (int half=0; half<2; half++){
                float t[4][4];
                #pragma unroll
                for (int i=0;i<4;i++){
                    int ii = half*4 + i;
                    unpack2(acc[ii][0], t[i][0], t[i][1]);
                    unpack2(acc[ii][1], t[i][2], t[i][3]);
                }
                #pragma unroll
                for (int cc=0; cc<4; cc++){
                    float4 v; v.x=t[0][cc]; v.y=t[1][cc]; v.z=t[2][cc]; v.w=t[3][cc];
                    *(float4*)(PS + (e0+cc)*36 + r0 + half*4) = v;
                }
            }
            __syncthreads();
            // group0 idle in epilogue (cheap)
        } else {
            #pragma unroll 4
            for (int k=0;k<256;k++){
                float4 av0 = *(const float4*)(msT + k*36 + r0);
                float4 av1 = *(const float4*)(msT + k*36 + r0 + 4);
                ulonglong2 Bv = *(const ulonglong2*)(g_WgT + (size_t)(Dq+k)*Dq + e0);
                u64 a;
                a = bcast2(av0.x); ffma2(acc[0][0],a,Bv.x); ffma2(acc[0][1],a,Bv.y);
                a = bcast2(av0.y); ffma2(acc[1][0],a,Bv.x); ffma2(acc[1][1],a,Bv.y);
                a = bcast2(av0.z); ffma2(acc[2][0],a,Bv.x); ffma2(acc[2][1],a,Bv.y);
                a = bcast2(av0.w); ffma2(acc[3][0],a,Bv.x); ffma2(acc[3][1],a,Bv.y);
                a = bcast2(av1.x); ffma2(acc[4][0],a,Bv.x); ffma2(acc[4][1],a,Bv.y);
                a = bcast2(av1.y); ffma2(acc[5][0],a,Bv.x); ffma2(acc[5][1],a,Bv.y);
                a = bcast2(av1.z); ffma2(acc[6][0],a,Bv.x); ffma2(acc[6][1],a,Bv.y);
                a = bcast2(av1.w); ffma2(acc[7][0],a,Bv.x); ffma2(acc[7][1],a,Bv.y);
            }
            __syncthreads();   // wait for group0's PS partial

            // epilogue: z = z1(PS) + z2(acc) + bg ; g = sigmoid ; out = x + g*mr
            float z[8][4];
            #pragma unroll
            for (int i=0;i<8;i++){
                unpack2(acc[i][0], z[i][0], z[i][1]);
                unpack2(acc[i][1], z[i][2], z[i][3]);
            }
            float4 bgv = *(const float4*)(bg + e0);
            float ob[8][4];
            #pragma unroll
            for (int j=0;j<4;j++){
                int e = e0 + j;
                float bj = (j==0?bgv.x : j==1?bgv.y : j==2?bgv.z : bgv.w);
                float4 p0 = *(const float4*)(PS  + e*36 + r0);
                float4 p1 = *(const float4*)(PS  + e*36 + r0 + 4);
                float4 m0 = *(const float4*)(msT + e*36 + r0);
                float4 m1 = *(const float4*)(msT + e*36 + r0 + 4);
                float4 x0 = *(const float4*)(xsT + e*RB + r0);
                float4 x1 = *(const float4*)(xsT + e*RB + r0 + 4);
                ob[0][j] = x0.x + sigmoidf_(z[0][j] + p0.x + bj) * m0.x;
                ob[1][j] = x0.y + sigmoidf_(z[1][j] + p0.y + bj) * m0.y;
                ob[2][j] = x0.z + sigmoidf_(z[2][j] + p0.z + bj) * m0.z;
                ob[3][j] = x0.w + sigmoidf_(z[3][j] + p0.w + bj) * m0.w;
                ob[4][j] = x1.x + sigmoidf_(z[4][j] + p1.x + bj) * m1.x;
                ob[5][j] = x1.y + sigmoidf_(z[5][j] + p1.y + bj) * m1.y;
                ob[6][j] = x1.z + sigmoidf_(z[6][j] + p1.z + bj) * m1.z;
                ob[7][j] = x1.w + sigmoidf_(z[7][j] + p1.w + bj) * m1.w;
            }
            #pragma unroll
            for (int i=0;i<8;i++){
                float4 v; v.x=ob[i][0]; v.y=ob[i][1]; v.z=ob[i][2]; v.w=ob[i][3];
                *(float4*)(out_enh + (size_t)(rowbase + r0 + i)*Dq + e0) = v;
            }
        }
    }
}

extern "C" void kernel_launch(void* const* d_in, const int* in_sizes, int n_in,
                              void* d_out, int out_size)
{
    const float* x    = (const float*)d_in[0];
    const float* memv = (const float*)d_in[1];
    const float* wg   = (const float*)d_in[2];
    const float* bg   = (const float*)d_in[3];

    float* out_enh = (float*)d_out;                       // (B,S,D) first
    float* out_w   = out_enh + (size_t)NROWS * Dq;        // then (B,S,M)

    const size_t smem_bytes = (size_t)SMEM_FLOATS * sizeof(float);  // 216 KB
    cudaFuncSetAttribute(vm_fused, cudaFuncAttributeMaxDynamicSharedMemorySize, (int)smem_bytes);

    vm_prep<<<(Mq*Dq + 255)/256, 256>>>(memv, wg);
    vm_fused<<<NROWS/RB, NT, smem_bytes>>>(x, memv, bg, out_enh, out_w);
}

// round 8
// speedup vs baseline: 1.0022x; 1.0022x over previous
#include <cuda_runtime.h>
#include <math.h>

#define Dq 256
#define Mq 512
#define RB 32
#define NT 512
#define NROWS (32*4096)

// SMEM float offsets
#define XS_OFF   0                        // xsT [256][32]  k-major
#define WS_OFF   (XS_OFF + Dq*RB)         // wsT [512][36]  logits/weights (group0 partial)
#define MS_OFF   (WS_OFF + Mq*36)         // msT [256][36]  memory_read
#define PS_OFF   (MS_OFF + Dq*36)         // PS  [512][36]  partial-sum scratch
#define R1_OFF   (PS_OFF + Mq*36)
#define R2_OFF   (R1_OFF + 512)
#define SMEM_FLOATS (R2_OFF + 512)        // 55296 floats = 216 KB

__device__ float g_memT[Dq*Mq];   // [k][m]  = memory[m][k]
__device__ float g_WgT[2*Dq*Dq];  // [dc][e] = Wg[e][dc]

typedef unsigned long long u64;

__device__ __forceinline__ u64 bcast2(float v){
    u64 r; asm("mov.b64 %0, {%1, %1};" : "=l"(r) : "f"(v)); return r;
}
__device__ __forceinline__ void unpack2(u64 v, float& lo, float& hi){
    asm("mov.b64 {%0, %1}, %2;" : "=f"(lo), "=f"(hi) : "l"(v));
}
__device__ __forceinline__ void ffma2(u64& d, u64 a, u64 b){
    asm("fma.rn.f32x2 %0, %1, %2, %0;" : "+l"(d) : "l"(a), "l"(b));
}
__device__ __forceinline__ float sigmoidf_(float p){
    return 1.f/(1.f+__expf(-p));
}

__global__ void vm_prep(const float* __restrict__ mem, const float* __restrict__ wg){
    int idx = blockIdx.x*blockDim.x + threadIdx.x;
    if (idx < Mq*Dq){
        int m = idx >> 8, k = idx & 255;      // memory: [512][256]
        g_memT[k*Mq + m] = mem[idx];
        int e = idx >> 9, dc = idx & 511;     // Wg: [256][512]
        g_WgT[dc*Dq + e] = wg[idx];
    }
}

__global__ __launch_bounds__(NT, 1)
void vm_fused(const float* __restrict__ x,
              const float* __restrict__ memv,
              const float* __restrict__ bg,
              float* __restrict__ out_enh,
              float* __restrict__ out_w)
{
    extern __shared__ float smem[];
    float* xsT  = smem + XS_OFF;   // [k][32]
    float* wsT  = smem + WS_OFF;   // [k][36]
    float* msT  = smem + MS_OFF;   // [k][36]
    float* PS   = smem + PS_OFF;   // [k][36]
    float* red1 = smem + R1_OFF;
    float* red2 = smem + R2_OFF;

    const int tid = threadIdx.x;
    const int rowbase = blockIdx.x * RB;
    const int wid = tid >> 5, lane = tid & 31;

    const int kh = wid >> 3;           // 0/1 : k-split group
    const int wc = wid & 7;            // col-block within group
    const int row_g = lane >> 3;       // 0..3
    const int col_o = lane & 7;        // 0..7
    const int r0 = row_g * 8;          // 8 rows per lane

    // ---------------- Phase A: x block -> xsT[k][r] (k-major) --------------
    {
        int r = lane;
        #pragma unroll
        for (int cc = 0; cc < 4; cc++){
            int c4 = wid + cc*16;
            float4 v = *(const float4*)(x + (size_t)(rowbase + r)*Dq + c4*4);
            xsT[(c4*4+0)*RB + r] = v.x;
            xsT[(c4*4+1)*RB + r] = v.y;
            xsT[(c4*4+2)*RB + r] = v.z;
            xsT[(c4*4+3)*RB + r] = v.w;
        }
    }
    __syncthreads();

    // ---------------- Phase B: logits = x @ memory^T  (k-split) ------------
    // group kh handles k in [kh*128, kh*128+128). warp: 32 rows x 64 cols.
    // lane: 8 rows x 8 cols (two 4-col strips). group0 -> wsT, group1 -> PS.
    {
        const int c0 = wc*64 + col_o*4;
        const int c1 = c0 + 32;
        const int kb = kh * 128;
        u64 acc[8][4];
        #pragma unroll
        for (int i=0;i<8;i++){ acc[i][0]=0; acc[i][1]=0; acc[i][2]=0; acc[i][3]=0; }

        #pragma unroll 4
        for (int k=0;k<128;k++){
            const int kk = kb + k;
            float4 av0 = *(const float4*)(xsT + kk*RB + r0);
            float4 av1 = *(const float4*)(xsT + kk*RB + r0 + 4);
            ulonglong2 B0 = *(const ulonglong2*)(g_memT + kk*Mq + c0);
            ulonglong2 B1 = *(const ulonglong2*)(g_memT + kk*Mq + c1);
            u64 a;
            a = bcast2(av0.x); ffma2(acc[0][0],a,B0.x); ffma2(acc[0][1],a,B0.y); ffma2(acc[0][2],a,B1.x); ffma2(acc[0][3],a,B1.y);
            a = bcast2(av0.y); ffma2(acc[1][0],a,B0.x); ffma2(acc[1][1],a,B0.y); ffma2(acc[1][2],a,B1.x); ffma2(acc[1][3],a,B1.y);
            a = bcast2(av0.z); ffma2(acc[2][0],a,B0.x); ffma2(acc[2][1],a,B0.y); ffma2(acc[2][2],a,B1.x); ffma2(acc[2][3],a,B1.y);
            a = bcast2(av0.w); ffma2(acc[3][0],a,B0.x); ffma2(acc[3][1],a,B0.y); ffma2(acc[3][2],a,B1.x); ffma2(acc[3][3],a,B1.y);
            a = bcast2(av1.x); ffma2(acc[4][0],a,B0.x); ffma2(acc[4][1],a,B0.y); ffma2(acc[4][2],a,B1.x); ffma2(acc[4][3],a,B1.y);
            a = bcast2(av1.y); ffma2(acc[5][0],a,B0.x); ffma2(acc[5][1],a,B0.y); ffma2(acc[5][2],a,B1.x); ffma2(acc[5][3],a,B1.y);
            a = bcast2(av1.z); ffma2(acc[6][0],a,B0.x); ffma2(acc[6][1],a,B0.y); ffma2(acc[6][2],a,B1.x); ffma2(acc[6][3],a,B1.y);
            a = bcast2(av1.w); ffma2(acc[7][0],a,B0.x); ffma2(acc[7][1],a,B0.y); ffma2(acc[7][2],a,B1.x); ffma2(acc[7][3],a,B1.y);
        }

        float* dst = (kh == 0) ? wsT : PS;
        #pragma unroll
        for (int half=0; half<2; half++){
            float t[4][8];
            #pragma unroll
            for (int i=0;i<4;i++){
                int ii = half*4 + i;
                unpack2(acc[ii][0], t[i][0], t[i][1]);
                unpack2(acc[ii][1], t[i][2], t[i][3]);
                unpack2(acc[ii][2], t[i][4], t[i][5]);
                unpack2(acc[ii][3], t[i][6], t[i][7]);
            }
            #pragma unroll
            for (int cc=0; cc<8; cc++){
                int col = (cc<4) ? (c0+cc) : (c1+cc-4);
                float4 v; v.x=t[0][cc]; v.y=t[1][cc]; v.z=t[2][cc]; v.w=t[3][cc];
                *(float4*)(dst + col*36 + r0 + half*4) = v;
            }
        }
    }
    __syncthreads();

    // ---------------- Phase C: reduce partials + softmax -------------------
    // warp w owns k-block [w*32, w*32+32); lane = row.
    {
        const int k0 = wid*32;
        float v[32];
        float mx = -3.402823466e38f;
        #pragma unroll
        for (int j=0;j<32;j++){
            v[j] = wsT[(k0+j)*36 + lane] + PS[(k0+j)*36 + lane];
            mx = fmaxf(mx, v[j]);
        }
        red1[wid*32 + lane] = mx;
        __syncthreads();
        float rm = -3.402823466e38f;
        #pragma unroll
        for (int i=0;i<16;i++) rm = fmaxf(rm, red1[i*32 + lane]);
        float sm = 0.f;
        #pragma unroll
        for (int j=0;j<32;j++){ v[j] = __expf(v[j]-rm); sm += v[j]; }
        red2[wid*32 + lane] = sm;
        __syncthreads();
        float rs = 0.f;
        #pragma unroll
        for (int i=0;i<16;i++) rs += red2[i*32 + lane];
        float inv = 1.f / rs;
        #pragma unroll
        for (int j=0;j<32;j++) wsT[(k0+j)*36 + lane] = v[j]*inv;
        __syncthreads();
        // coalesced out_w writeout (warp = 2 rows)
        #pragma unroll
        for (int rr=0; rr<2; rr++){
            int r = wid*2 + rr;
            float* wout = out_w + (size_t)(rowbase + r)*Mq;
            #pragma unroll
            for (int t=0;t<16;t++)
                wout[lane + 32*t] = wsT[(lane + 32*t)*36 + r];
        }
    }

    // ---------------- Phase D: mr = w @ memory  (k-split, K=512) -----------
    // group kh: k in [kh*256, +256). warp: 32 rows x 32 cols, lane 8x4.
    {
        const int c0 = wc*32 + col_o*4;
        const int kb = kh * 256;
        u64 acc[8][2];
        #pragma unroll
        for (int i=0;i<8;i++){ acc[i][0]=0; acc[i][1]=0; }
        #pragma unroll 4
        for (int k=0;k<256;k++){
            const int kk = kb + k;
            float4 av0 = *(const float4*)(wsT + kk*36 + r0);
            float4 av1 = *(const float4*)(wsT + kk*36 + r0 + 4);
            ulonglong2 Bv = *(const ulonglong2*)(memv + kk*Dq + c0);
            u64 a;
            a = bcast2(av0.x); ffma2(acc[0][0],a,Bv.x); ffma2(acc[0][1],a,Bv.y);
            a = bcast2(av0.y); ffma2(acc[1][0],a,Bv.x); ffma2(acc[1][1],a,Bv.y);
            a = bcast2(av0.z); ffma2(acc[2][0],a,Bv.x); ffma2(acc[2][1],a,Bv.y);
            a = bcast2(av0.w); ffma2(acc[3][0],a,Bv.x); ffma2(acc[3][1],a,Bv.y);
            a = bcast2(av1.x); ffma2(acc[4][0],a,Bv.x); ffma2(acc[4][1],a,Bv.y);
            a = bcast2(av1.y); ffma2(acc[5][0],a,Bv.x); ffma2(acc[5][1],a,Bv.y);
            a = bcast2(av1.z); ffma2(acc[6][0],a,Bv.x); ffma2(acc[6][1],a,Bv.y);
            a = bcast2(av1.w); ffma2(acc[7][0],a,Bv.x); ffma2(acc[7][1],a,Bv.y);
        }
        float* dst = (kh == 0) ? msT : PS;
        #pragma unroll
        for (int half=0; half<2; half++){
            float t[4][4];
            #pragma unroll
            for (int i=0;i<4;i++){
                int ii = half*4 + i;
                unpack2(acc[ii][0], t[i][0], t[i][1]);
                unpack2(acc[ii][1], t[i][2], t[i][3]);
            }
            #pragma unroll
            for (int cc=0; cc<4; cc++){
                float4 v; v.x=t[0][cc]; v.y=t[1][cc]; v.z=t[2][cc]; v.w=t[3][cc];
                *(float4*)(msT == dst ? (msT + (c0+cc)*36 + r0 + half*4)
                                      : (PS  + (c0+cc)*36 + r0 + half*4)) = v;
            }
        }
    }
    __syncthreads();
    // reduce PS into msT: 256 cols x 32 rows
    {
        #pragma unroll
        for (int t=0;t<16;t++){
            int idx = tid + t*512;          // 0..8191
            int col = idx >> 5, row = idx & 31;
            msT[col*36 + row] += PS[col*36 + row];
        }
    }
    __syncthreads();

    // ---------------- Phase E: gate GEMMs (group0: W1.x, group1: W2.mr) ----
    {
        const int e0 = wc*32 + col_o*4;
        u64 acc[8][2];
        #pragma unroll
        for (int i=0;i<8;i++){ acc[i][0]=0; acc[i][1]=0; }

        if (kh == 0){
            #pragma unroll 4
            for (int k=0;k<256;k++){
                float4 av0 = *(const float4*)(xsT + k*RB + r0);
                float4 av1 = *(const float4*)(xsT + k*RB + r0 + 4);
                ulonglong2 Bv = *(const ulonglong2*)(g_WgT + (size_t)k*Dq + e0);
                u64 a;
                a = bcast2(av0.x); ffma2(acc[0][0],a,Bv.x); ffma2(acc[0][1],a,Bv.y);
                a = bcast2(av0.y); ffma2(acc[1][0],a,Bv.x); ffma2(acc[1][1],a,Bv.y);
                a = bcast2(av0.z); ffma2(acc[2][0],a,Bv.x); ffma2(acc[2][1],a,Bv.y);
                a = bcast2(av0.w); ffma2(acc[3][0],a,Bv.x); ffma2(acc[3][1],a,Bv.y);
                a = bcast2(av1.x); ffma2(acc[4][0],a,Bv.x); ffma2(acc[4][1],a,Bv.y);
                a = bcast2(av1.y); ffma2(acc[5][0],a,Bv.x); ffma2(acc[5][1],a,Bv.y);
                a = bcast2(av1.z); ffma2(acc[6][0],a,Bv.x); ffma2(acc[6][1],a,Bv.y);
                a = bcast2(av1.w); ffma2(acc[7][0],a,Bv.x); ffma2(acc[7][1],a,Bv.y);
            }
            // store partial z1 to PS
            #pragma unroll
            for (int half=0; half<2; half++){
                float t[4][4];
                #pragma unroll
                for (int i=0;i<4;i++){
                    int ii = half*4 + i;
                    unpack2(acc[ii][0], t[i][0], t[i][1]);
                    unpack2(acc[ii][1], t[i][2], t[i][3]);
                }
                #pragma unroll
                for (int cc=0; cc<4; cc++){
                    float4 v; v.x=t[0][cc]; v.y=t[1][cc]; v.z=t[2][cc]; v.w=t[3][cc];
                    *(float4*)(PS + (e0+cc)*36 + r0 + half*4) = v;
                }
            }
            __syncthreads();
            // group0 idle in epilogue (cheap)
        } else {
            #pragma unroll 4
            for (int k=0;k<256;k++){
                float4 av0 = *(const float4*)(msT + k*36 + r0);
                float4 av1 = *(const float4*)(msT + k*36 + r0 + 4);
                ulonglong2 Bv = *(const ulonglong2*)(g_WgT + (size_t)(Dq+k)*Dq + e0);
                u64 a;
                a = bcast2(av0.x); ffma2(acc[0][0],a,Bv.x); ffma2(acc[0][1],a,Bv.y);
                a = bcast2(av0.y); ffma2(acc[1][0],a,Bv.x); ffma2(acc[1][1],a,Bv.y);
                a = bcast2(av0.z); ffma2(acc[2][0],a,Bv.x); ffma2(acc[2][1],a,Bv.y);
                a = bcast2(av0.w); ffma2(acc[3][0],a,Bv.x); ffma2(acc[3][1],a,Bv.y);
                a = bcast2(av1.x); ffma2(acc[4][0],a,Bv.x); ffma2(acc[4][1],a,Bv.y);
                a = bcast2(av1.y); ffma2(acc[5][0],a,Bv.x); ffma2(acc[5][1],a,Bv.y);
                a = bcast2(av1.z); ffma2(acc[6][0],a,Bv.x); ffma2(acc[6][1],a,Bv.y);
                a = bcast2(av1.w); ffma2(acc[7][0],a,Bv.x); ffma2(acc[7][1],a,Bv.y);
            }
            __syncthreads();   // wait for group0's PS partial

            // epilogue: z = z1(PS) + z2(acc) + bg ; g = sigmoid ; out = x + g*mr
            float z[8][4];
            #pragma unroll
            for (int i=0;i<8;i++){
                unpack2(acc[i][0], z[i][0], z[i][1]);
                unpack2(acc[i][1], z[i][2], z[i][3]);
            }
            float4 bgv = *(const float4*)(bg + e0);
            float ob[8][4];
            #pragma unroll
            for (int j=0;j<4;j++){
                int e = e0 + j;
                float bj = (j==0?bgv.x : j==1?bgv.y : j==2?bgv.z : bgv.w);
                float4 p0 = *(const float4*)(PS  + e*36 + r0);
                float4 p1 = *(const float4*)(PS  + e*36 + r0 + 4);
                float4 m0 = *(const float4*)(msT + e*36 + r0);
                float4 m1 = *(const float4*)(msT + e*36 + r0 + 4);
                float4 x0 = *(const float4*)(xsT + e*RB + r0);
                float4 x1 = *(const float4*)(xsT + e*RB + r0 + 4);
                ob[0][j] = x0.x + sigmoidf_(z[0][j] + p0.x + bj) * m0.x;
                ob[1][j] = x0.y + sigmoidf_(z[1][j] + p0.y + bj) * m0.y;
                ob[2][j] = x0.z + sigmoidf_(z[2][j] + p0.z + bj) * m0.z;
                ob[3][j] = x0.w + sigmoidf_(z[3][j] + p0.w + bj) * m0.w;
                ob[4][j] = x1.x + sigmoidf_(z[4][j] + p1.x + bj) * m1.x;
                ob[5][j] = x1.y + sigmoidf_(z[5][j] + p1.y + bj) * m1.y;
                ob[6][j] = x1.z + sigmoidf_(z[6][j] + p1.z + bj) * m1.z;
                ob[7][j] = x1.w + sigmoidf_(z[7][j] + p1.w + bj) * m1.w;
            }
            #pragma unroll
            for (int i=0;i<8;i++){
                float4 v; v.x=ob[i][0]; v.y=ob[i][1]; v.z=ob[i][2]; v.w=ob[i][3];
                *(float4*)(out_enh + (size_t)(rowbase + r0 + i)*Dq + e0) = v;
            }
        }
    }
}

extern "C" void kernel_launch(void* const* d_in, const int* in_sizes, int n_in,
                              void* d_out, int out_size)
{
    const float* x    = (const float*)d_in[0];
    const float* memv = (const float*)d_in[1];
    const float* wg   = (const float*)d_in[2];
    const float* bg   = (const float*)d_in[3];

    float* out_enh = (float*)d_out;                       // (B,S,D) first
    float* out_w   = out_enh + (size_t)NROWS * Dq;        // then (B,S,M)

    const size_t smem_bytes = (size_t)SMEM_FLOATS * sizeof(float);  // 216 KB
    cudaFuncSetAttribute(vm_fused, cudaFuncAttributeMaxDynamicSharedMemorySize, (int)smem_bytes);

    vm_prep<<<(Mq*Dq + 255)/256, 256>>>(memv, wg);
    vm_fused<<<NROWS/RB, NT, smem_bytes>>>(x, memv, bg, out_enh, out_w);
}

// round 11
// speedup vs baseline: 1.5609x; 1.5575x over previous
#include <cuda_runtime.h>
#include <cuda_bf16.h>
#include <stdint.h>
#include <math.h>

#define Dq 256
#define Mq 512
#define RB 64
#define NT 256
#define NROWS (32*4096)

// ---- SMEM byte offsets ----
// R region: per-row slot of RP bytes. Holds fp32 logits [64][512] (pitch RP),
// then in-place: w_hi bf16 [512] @ +0, w_lo @ +RLO. Later: mr_hi/lo (256 cols).
#define R_OFF  0
#define RP     2096
#define RLO    1040
// X region: x split. hi [256]bf16 @ +0, lo @ +XLO, pitch XP.
#define X_OFF  134144
#define XP     1104
#define XLO    560
// B staging: [128 rows][32 k] bf16, pitch 80B. hi and lo matrices.
#define BH_OFF 204800
#define BL_OFF 215040
#define BDELTA (BL_OFF - BH_OFF)
#define BG_OFF 225280
#define SMEM_BYTES 226304

// pre-split bf16 operands (L2-resident, ~1.5MB)
__device__ __align__(16) __nv_bfloat16 g_memB_h[Mq*Dq], g_memB_l[Mq*Dq]; // [m][k]
__device__ __align__(16) __nv_bfloat16 g_memT_h[Dq*Mq], g_memT_l[Dq*Mq]; // [d][m]
__device__ __align__(16) __nv_bfloat16 g_wg_h[Dq*Mq],   g_wg_l[Dq*Mq];   // [e][dc] = Wg row-major

__device__ __forceinline__ uint32_t smem_u32(const void* p){
    uint32_t a;
    asm("{ .reg .u64 t; cvta.to.shared.u64 t, %1; cvt.u32.u64 %0, t; }" : "=r"(a) : "l"(p));
    return a;
}
__device__ __forceinline__ void split_bf(float v, __nv_bfloat16& h, __nv_bfloat16& l){
    h = __float2bfloat16(v);
    l = __float2bfloat16(v - __bfloat162float(h));
}
__device__ __forceinline__ uint32_t pk2(__nv_bfloat16 a, __nv_bfloat16 b){
    uint16_t ua = *(uint16_t*)&a, ub = *(uint16_t*)&b;
    return (uint32_t)ua | ((uint32_t)ub << 16);
}
__device__ __forceinline__ float bf2sum(uint32_t h, uint32_t l, int hi){
    uint16_t uh = hi ? (uint16_t)(h >> 16) : (uint16_t)h;
    uint16_t ul = hi ? (uint16_t)(l >> 16) : (uint16_t)l;
    __nv_bfloat16 bh = *(__nv_bfloat16*)&uh, bl = *(__nv_bfloat16*)&ul;
    return __bfloat162float(bh) + __bfloat162float(bl);
}
__device__ __forceinline__ void ldsm4(unsigned* a, uint32_t addr){
    asm volatile("ldmatrix.sync.aligned.m8n8.x4.shared.b16 {%0,%1,%2,%3}, [%4];"
        : "=r"(a[0]), "=r"(a[1]), "=r"(a[2]), "=r"(a[3]) : "r"(addr));
}
__device__ __forceinline__ void ldsm2(unsigned* b, uint32_t addr){
    asm volatile("ldmatrix.sync.aligned.m8n8.x2.shared.b16 {%0,%1}, [%2];"
        : "=r"(b[0]), "=r"(b[1]) : "r"(addr));
}
__device__ __forceinline__ void mma(float* d, const unsigned* a, const unsigned* b){
    asm volatile("mma.sync.aligned.m16n8k16.row.col.f32.bf16.bf16.f32 "
        "{%0,%1,%2,%3}, {%4,%5,%6,%7}, {%8,%9}, {%0,%1,%2,%3};"
        : "+f"(d[0]), "+f"(d[1]), "+f"(d[2]), "+f"(d[3])
        : "r"(a[0]), "r"(a[1]), "r"(a[2]), "r"(a[3]), "r"(b[0]), "r"(b[1]));
}

// stage [128 rows][32 k] hi+lo tiles from global into BH/BL (pitch 80B)
__device__ __forceinline__ void stage(char* sm, const __nv_bfloat16* gh,
        const __nv_bfloat16* gl, int row0, int gs, int col0){
    const int tid = threadIdx.x;
    #pragma unroll
    for (int p = 0; p < 2; p++){
        int idx = tid + p*NT;                 // 0..511
        int row = idx >> 2, c = idx & 3;
        size_t go = (size_t)(row0 + row)*gs + col0 + c*8;
        *(uint4*)(sm + BH_OFF + row*80 + c*16) = *(const uint4*)(gh + go);
        *(uint4*)(sm + BL_OFF + row*80 + c*16) = *(const uint4*)(gl + go);
    }
}

// one k=32 chunk of split GEMM: acc[mt][nb][4] += A(sm)·B(staged)
__device__ __forceinline__ void gemm_k32(float acc[2][4][4],
        uint32_t a0, uint32_t a1, uint32_t alo, uint32_t bb){
    #pragma unroll
    for (int ki = 0; ki < 2; ki++){
        unsigned ah0[4], al0[4], ah1[4], al1[4];
        ldsm4(ah0, a0 + ki*32); ldsm4(al0, a0 + alo + ki*32);
        ldsm4(ah1, a1 + ki*32); ldsm4(al1, a1 + alo + ki*32);
        #pragma unroll
        for (int nb = 0; nb < 4; nb++){
            unsigned bh[2], bl[2];
            uint32_t ba = bb + nb*640 + ki*32;
            ldsm2(bh, ba); ldsm2(bl, ba + BDELTA);
            mma(acc[0][nb], ah0, bh); mma(acc[1][nb], ah1, bh);
            mma(acc[0][nb], ah0, bl); mma(acc[1][nb], ah1, bl);
            mma(acc[0][nb], al0, bh); mma(acc[1][nb], al1, bh);
        }
    }
}

__global__ void vm_prep(const float* __restrict__ mem, const float* __restrict__ wg){
    int idx = blockIdx.x*blockDim.x + threadIdx.x;
    if (idx < Mq*Dq){
        int m = idx >> 8, k = idx & 255;
        __nv_bfloat16 h, l;
        split_bf(mem[idx], h, l);
        g_memB_h[idx] = h;          g_memB_l[idx] = l;
        g_memT_h[k*Mq + m] = h;     g_memT_l[k*Mq + m] = l;
        // Wg row-major [e][dc]: e = output gate index (row), dc = contraction (col)
        split_bf(wg[idx], h, l);
        g_wg_h[idx] = h;            g_wg_l[idx] = l;
    }
}

__global__ __launch_bounds__(NT, 1)
void vm_fused(const float* __restrict__ x,
              const float* __restrict__ bg,
              float* __restrict__ out_enh,
              float* __restrict__ out_w)
{
    extern __shared__ char sm[];
    const uint32_t sm32 = smem_u32(sm);
    float* bg_s = (float*)(sm + BG_OFF);

    const int tid = threadIdx.x;
    const int wid = tid >> 5, lane = tid & 31;
    const int mw = wid & 1, nw = wid >> 1;          // warp grid 2 (m) x 4 (n)
    const int rowbase = blockIdx.x * RB;

    if (tid < Dq) bg_s[tid] = bg[tid];

    // per-lane ldmatrix base addrs (A from X region, A from R region, B staging)
    const uint32_t aX0 = sm32 + X_OFF + (mw*32 + (lane&15))*XP + (lane>>4)*16;
    const uint32_t aX1 = aX0 + 16*XP;
    const uint32_t aR0 = sm32 + R_OFF + (mw*32 + (lane&15))*RP + (lane>>4)*16;
    const uint32_t aR1 = aR0 + 16*RP;
    const uint32_t bB  = sm32 + BH_OFF + (nw*32 + (lane&7))*80 + ((lane>>3)&1)*16;

    // ---------------- Phase A: x -> split bf16 in X region -----------------
    #pragma unroll
    for (int p = 0; p < 16; p++){
        int idx = tid + p*NT;                // 4096 float4s
        int r = idx >> 6, c4 = idx & 63;
        float4 v = *(const float4*)(x + (size_t)(rowbase + r)*Dq + c4*4);
        __nv_bfloat16 h0,l0,h1,l1,h2,l2,h3,l3;
        split_bf(v.x,h0,l0); split_bf(v.y,h1,l1); split_bf(v.z,h2,l2); split_bf(v.w,h3,l3);
        *(uint2*)(sm + X_OFF + r*XP + c4*8)       = make_uint2(pk2(h0,h1), pk2(h2,h3));
        *(uint2*)(sm + X_OFF + r*XP + XLO + c4*8) = make_uint2(pk2(l0,l1), pk2(l2,l3));
    }

    // ---------------- Phase B: logits = x @ memory^T -----------------------
    for (int nc = 0; nc < 4; nc++){
        float acc[2][4][4];
        #pragma unroll
        for (int i=0;i<2;i++) for (int j=0;j<4;j++) for (int t=0;t<4;t++) acc[i][j][t]=0.f;
        for (int kc = 0; kc < 8; kc++){
            stage(sm, g_memB_h, g_memB_l, nc*128, Dq, kc*32);
            __syncthreads();
            gemm_k32(acc, aX0 + kc*64, aX1 + kc*64, XLO, bB);
            __syncthreads();
        }
        // store fp32 logits
        #pragma unroll
        for (int mt = 0; mt < 2; mt++)
            #pragma unroll
            for (int nb = 0; nb < 4; nb++){
                int r = mw*32 + mt*16 + (lane>>2);
                int c = nc*128 + nw*32 + nb*8 + 2*(lane&3);
                *(float2*)(sm + R_OFF + r*RP + c*4)     = make_float2(acc[mt][nb][0], acc[mt][nb][1]);
                *(float2*)(sm + R_OFF + (r+8)*RP + c*4) = make_float2(acc[mt][nb][2], acc[mt][nb][3]);
            }
    }
    __syncthreads();

    // ---------------- Phase C: softmax + out_w + in-place split ------------
    for (int t = 0; t < 8; t++){
        int r = wid*8 + t;
        char* rbase = sm + R_OFF + r*RP;
        float v[16];
        #pragma unroll
        for (int j = 0; j < 8; j++){
            float2 p = *(float2*)(rbase + (2*lane + 64*j)*4);
            v[2*j] = p.x; v[2*j+1] = p.y;
        }
        float mx = v[0];
        #pragma unroll
        for (int i = 1; i < 16; i++) mx = fmaxf(mx, v[i]);
        #pragma unroll
        for (int o = 16; o > 0; o >>= 1) mx = fmaxf(mx, __shfl_xor_sync(~0u, mx, o));
        float s = 0.f;
        #pragma unroll
        for (int i = 0; i < 16; i++){ v[i] = __expf(v[i] - mx); s += v[i]; }
        #pragma unroll
        for (int o = 16; o > 0; o >>= 1) s += __shfl_xor_sync(~0u, s, o);
        float inv = 1.f / s;
        float* wout = out_w + (size_t)(rowbase + r)*Mq;
        #pragma unroll
        for (int j = 0; j < 8; j++){
            float w0 = v[2*j]*inv, w1 = v[2*j+1]*inv;
            v[2*j] = w0; v[2*j+1] = w1;
            *(float2*)(wout + 2*lane + 64*j) = make_float2(w0, w1);
        }
        __syncwarp();
        #pragma unroll
        for (int j = 0; j < 8; j++){
            __nv_bfloat16 h0,l0,h1,l1;
            split_bf(v[2*j], h0, l0); split_bf(v[2*j+1], h1, l1);
            int c = 2*lane + 64*j;
            *(uint32_t*)(rbase + 2*c)       = pk2(h0, h1);
            *(uint32_t*)(rbase + RLO + 2*c) = pk2(l0, l1);
        }
    }
    __syncthreads();

    // ---------------- Phase D: mr = w @ memory (accums in regs) ------------
    float dacc[2][2][4][4];
    #pragma unroll
    for (int n=0;n<2;n++) for (int i=0;i<2;i++) for (int j=0;j<4;j++) for (int t=0;t<4;t++)
        dacc[n][i][j][t] = 0.f;
    for (int nc = 0; nc < 2; nc++){
        for (int kc = 0; kc < 16; kc++){
            stage(sm, g_memT_h, g_memT_l, nc*128, Mq, kc*32);
            __syncthreads();
            gemm_k32(dacc[nc], aR0 + kc*64, aR1 + kc*64, RLO, bB);
            __syncthreads();
        }
    }
    // write mr split into R region (W fully consumed)
    #pragma unroll
    for (int nc = 0; nc < 2; nc++)
        #pragma unroll
        for (int mt = 0; mt < 2; mt++)
            #pragma unroll
            for (int nb = 0; nb < 4; nb++){
                int r = mw*32 + mt*16 + (lane>>2);
                int c = nc*128 + nw*32 + nb*8 + 2*(lane&3);
                __nv_bfloat16 h0,l0,h1,l1;
                split_bf(dacc[nc][mt][nb][0], h0, l0); split_bf(dacc[nc][mt][nb][1], h1, l1);
                *(uint32_t*)(sm + R_OFF + r*RP + 2*c)       = pk2(h0,h1);
                *(uint32_t*)(sm + R_OFF + r*RP + RLO + 2*c) = pk2(l0,l1);
                split_bf(dacc[nc][mt][nb][2], h0, l0); split_bf(dacc[nc][mt][nb][3], h1, l1);
                *(uint32_t*)(sm + R_OFF + (r+8)*RP + 2*c)       = pk2(h0,h1);
                *(uint32_t*)(sm + R_OFF + (r+8)*RP + RLO + 2*c) = pk2(l0,l1);
            }
    __syncthreads();

    // ---------------- Phase E: gate = x@W1 + mr@W2, epilogue ---------------
    // z[r][e] = sum_d x[r][d]*Wg[e][d] + sum_d mr[r][d]*Wg[e][256+d]
    // B[n=e][k=d] = Wg row-major directly (no transpose).
    for (int nc = 0; nc < 2; nc++){
        float gacc[2][4][4];
        #pragma unroll
        for (int i=0;i<2;i++) for (int j=0;j<4;j++) for (int t=0;t<4;t++) gacc[i][j][t]=0.f;
        for (int kc = 0; kc < 8; kc++){          // part 1: A = x, B = Wg[:, 0:256]
            stage(sm, g_wg_h, g_wg_l, nc*128, Mq, kc*32);
            __syncthreads();
            gemm_k32(gacc, aX0 + kc*64, aX1 + kc*64, XLO, bB);
            __syncthreads();
        }
        for (int kc = 0; kc < 8; kc++){          // part 2: A = mr, B = Wg[:, 256:512]
            stage(sm, g_wg_h, g_wg_l, nc*128, Mq, 256 + kc*32);
            __syncthreads();
            gemm_k32(gacc, aR0 + kc*64, aR1 + kc*64, RLO, bB);
            __syncthreads();
        }
        // epilogue: enhanced = x + sigmoid(z+bg)*mr
        #pragma unroll
        for (int mt = 0; mt < 2; mt++)
            #pragma unroll
            for (int nb = 0; nb < 4; nb++){
                int e = nc*128 + nw*32 + nb*8 + 2*(lane&3);
                float b0 = bg_s[e], b1 = bg_s[e+1];
                #pragma unroll
                for (int rh = 0; rh < 2; rh++){
                    int r = mw*32 + mt*16 + (lane>>2) + rh*8;
                    float z0 = gacc[mt][nb][rh*2]   + b0;
                    float z1 = gacc[mt][nb][rh*2+1] + b1;
                    uint32_t xh = *(uint32_t*)(sm + X_OFF + r*XP + 2*e);
                    uint32_t xl = *(uint32_t*)(sm + X_OFF + r*XP + XLO + 2*e);
                    uint32_t mh = *(uint32_t*)(sm + R_OFF + r*RP + 2*e);
                    uint32_t ml = *(uint32_t*)(sm + R_OFF + r*RP + RLO + 2*e);
                    float x0 = bf2sum(xh, xl, 0), x1 = bf2sum(xh, xl, 1);
                    float m0 = bf2sum(mh, ml, 0), m1 = bf2sum(mh, ml, 1);
                    float g0 = 1.f/(1.f + __expf(-z0));
                    float g1 = 1.f/(1.f + __expf(-z1));
                    *(float2*)(out_enh + (size_t)(rowbase + r)*Dq + e) =
                        make_float2(x0 + g0*m0, x1 + g1*m1);
                }
            }
    }
}

extern "C" void kernel_launch(void* const* d_in, const int* in_sizes, int n_in,
                              void* d_out, int out_size)
{
    const float* x    = (const float*)d_in[0];
    const float* memv = (const float*)d_in[1];
    const float* wg   = (const float*)d_in[2];
    const float* bg   = (const float*)d_in[3];

    float* out_enh = (float*)d_out;
    float* out_w   = out_enh + (size_t)NROWS * Dq;

    cudaFuncSetAttribute(vm_fused, cudaFuncAttributeMaxDynamicSharedMemorySize, SMEM_BYTES);

    vm_prep<<<(Mq*Dq + 511)/512, 512>>>(memv, wg);
    vm_fused<<<NROWS/RB, NT, SMEM_BYTES>>>(x, bg, out_enh, out_w);
}

// round 12
// speedup vs baseline: 2.2642x; 1.4505x over previous
#include <cuda_runtime.h>
#include <cuda_bf16.h>
#include <stdint.h>
#include <math.h>

#define Dq 256
#define Mq 512
#define RB 64
#define NT 512
#define NROWS (32*4096)

// ---- SMEM layout ----
// R region: 64 row-slots of RP bytes: fp32 logits [512] -> in-place w_hi/w_lo bf16 -> mr_hi/mr_lo
#define R_OFF  0
#define RP     2064
#define RLO    1040
// X region: x split bf16: hi[256] @ +0, lo @ +XLO
#define X_OFF  132096
#define XP     1040
#define XLO    528
// Staging: 2 buffers x (hi 8192 + lo 8192); rows of 64B, 16B-chunk XOR swizzle
#define ST_OFF 198656
#define SMEM_BYTES 231424

// pre-split bf16 operands (L2-resident, ~1.5MB)
__device__ __align__(16) __nv_bfloat16 g_memB_h[Mq*Dq], g_memB_l[Mq*Dq]; // [m][k]
__device__ __align__(16) __nv_bfloat16 g_memT_h[Dq*Mq], g_memT_l[Dq*Mq]; // [d][m]
__device__ __align__(16) __nv_bfloat16 g_wg_h[Dq*Mq],   g_wg_l[Dq*Mq];   // [e][dc] row-major

__device__ __forceinline__ uint32_t smem_u32(const void* p){
    uint32_t a;
    asm("{ .reg .u64 t; cvta.to.shared.u64 t, %1; cvt.u32.u64 %0, t; }" : "=r"(a) : "l"(p));
    return a;
}
__device__ __forceinline__ void split_bf(float v, __nv_bfloat16& h, __nv_bfloat16& l){
    h = __float2bfloat16(v);
    l = __float2bfloat16(v - __bfloat162float(h));
}
__device__ __forceinline__ uint32_t pk2(__nv_bfloat16 a, __nv_bfloat16 b){
    uint16_t ua = *(uint16_t*)&a, ub = *(uint16_t*)&b;
    return (uint32_t)ua | ((uint32_t)ub << 16);
}
__device__ __forceinline__ float bf2sum(uint32_t h, uint32_t l, int hi){
    uint16_t uh = hi ? (uint16_t)(h >> 16) : (uint16_t)h;
    uint16_t ul = hi ? (uint16_t)(l >> 16) : (uint16_t)l;
    __nv_bfloat16 bh = *(__nv_bfloat16*)&uh, bl = *(__nv_bfloat16*)&ul;
    return __bfloat162float(bh) + __bfloat162float(bl);
}
__device__ __forceinline__ void ldsm4(unsigned* a, uint32_t addr){
    asm volatile("ldmatrix.sync.aligned.m8n8.x4.shared.b16 {%0,%1,%2,%3}, [%4];"
        : "=r"(a[0]), "=r"(a[1]), "=r"(a[2]), "=r"(a[3]) : "r"(addr));
}
__device__ __forceinline__ void ldsm2(unsigned* b, uint32_t addr){
    asm volatile("ldmatrix.sync.aligned.m8n8.x2.shared.b16 {%0,%1}, [%2];"
        : "=r"(b[0]), "=r"(b[1]) : "r"(addr));
}
__device__ __forceinline__ void mma(float* d, const unsigned* a, const unsigned* b){
    asm volatile("mma.sync.aligned.m16n8k16.row.col.f32.bf16.bf16.f32 "
        "{%0,%1,%2,%3}, {%4,%5,%6,%7}, {%8,%9}, {%0,%1,%2,%3};"
        : "+f"(d[0]), "+f"(d[1]), "+f"(d[2]), "+f"(d[3])
        : "r"(a[0]), "r"(a[1]), "r"(a[2]), "r"(a[3]), "r"(b[0]), "r"(b[1]));
}
__device__ __forceinline__ void cpa16(uint32_t s, const void* g){
    asm volatile("cp.async.cg.shared.global [%0], [%1], 16;" :: "r"(s), "l"(g));
}
#define CP_COMMIT() asm volatile("cp.async.commit_group;" ::: "memory")
template<int N> __device__ __forceinline__ void cp_wait(){
    asm volatile("cp.async.wait_group %0;" :: "n"(N) : "memory");
}

// stage [128 rows][32 k] hi+lo into swizzled 64B-pitch buffer (512 threads: 1 chunk each)
__device__ __forceinline__ void stage2(uint32_t st, const __nv_bfloat16* gh,
        const __nv_bfloat16* gl, int row0, int gs, int col0){
    int idx = threadIdx.x;
    int row = idx >> 2, c = idx & 3;
    uint32_t sa = st + row*64 + ((c ^ ((row>>1)&3)) & 3)*16;
    size_t go = (size_t)(row0 + row)*gs + col0 + c*8;
    cpa16(sa, gh + go);
    cpa16(sa + 8192, gl + go);
}
__device__ __forceinline__ void stage1(uint32_t st, const __nv_bfloat16* gh,
        int row0, int gs, int col0){
    int idx = threadIdx.x;
    int row = idx >> 2, c = idx & 3;
    uint32_t sa = st + row*64 + ((c ^ ((row>>1)&3)) & 3)*16;
    cpa16(sa, gh + (size_t)(row0 + row)*gs + col0 + c*8);
}

// split GEMM chunk: A m32 (2 tiles) x B n16 (2 nb) x k32, 3-term split => 24 mma
__device__ __forceinline__ void gemm_split(float acc[2][2][4], uint32_t a0, uint32_t a1,
        uint32_t alo, uint32_t st, uint32_t bRB, uint32_t swk0, uint32_t swk1){
    #pragma unroll
    for (int ki = 0; ki < 2; ki++){
        unsigned ah0[4], al0[4], ah1[4], al1[4];
        ldsm4(ah0, a0 + ki*32); ldsm4(al0, a0 + alo + ki*32);
        ldsm4(ah1, a1 + ki*32); ldsm4(al1, a1 + alo + ki*32);
        uint32_t sw = ki ? swk1 : swk0;
        #pragma unroll
        for (int nb = 0; nb < 2; nb++){
            unsigned bh[2], bl[2];
            uint32_t ba = st + bRB + nb*512 + sw;
            ldsm2(bh, ba); ldsm2(bl, ba + 8192);
            mma(acc[0][nb], ah0, bh); mma(acc[1][nb], ah1, bh);
            mma(acc[0][nb], ah0, bl); mma(acc[1][nb], ah1, bl);
            mma(acc[0][nb], al0, bh); mma(acc[1][nb], al1, bh);
        }
    }
}
// hi-only GEMM chunk (gate): 8 mma
__device__ __forceinline__ void gemm_hi(float acc[2][2][4], uint32_t a0, uint32_t a1,
        uint32_t st, uint32_t bRB, uint32_t swk0, uint32_t swk1){
    #pragma unroll
    for (int ki = 0; ki < 2; ki++){
        unsigned ah0[4], ah1[4];
        ldsm4(ah0, a0 + ki*32); ldsm4(ah1, a1 + ki*32);
        uint32_t sw = ki ? swk1 : swk0;
        #pragma unroll
        for (int nb = 0; nb < 2; nb++){
            unsigned bh[2];
            ldsm2(bh, st + bRB + nb*512 + sw);
            mma(acc[0][nb], ah0, bh); mma(acc[1][nb], ah1, bh);
        }
    }
}

__global__ void vm_prep(const float* __restrict__ mem, const float* __restrict__ wg){
    int idx = blockIdx.x*blockDim.x + threadIdx.x;
    if (idx < Mq*Dq){
        int m = idx >> 8, k = idx & 255;
        __nv_bfloat16 h, l;
        split_bf(mem[idx], h, l);
        g_memB_h[idx] = h;          g_memB_l[idx] = l;
        g_memT_h[k*Mq + m] = h;     g_memT_l[k*Mq + m] = l;
        split_bf(wg[idx], h, l);    // Wg row-major [e][dc]
        g_wg_h[idx] = h;            g_wg_l[idx] = l;
    }
}

__global__ __launch_bounds__(NT, 1)
void vm_fused(const float* __restrict__ x,
              const float* __restrict__ bg,
              float* __restrict__ out_enh,
              float* __restrict__ out_w)
{
    extern __shared__ char sm[];
    const uint32_t sm32 = smem_u32(sm);
    const uint32_t ST0 = sm32 + ST_OFF, ST1 = ST0 + 16384;

    const int tid = threadIdx.x;
    const int wid = tid >> 5, lane = tid & 31;
    const int mw = wid & 1, nw = wid >> 1;          // warp grid 2(m) x 8(n)
    const int rowbase = blockIdx.x * RB;

    // per-lane A ldmatrix bases
    const uint32_t aX0 = sm32 + X_OFF + (mw*32 + (lane&15))*XP + (lane>>4)*16;
    const uint32_t aX1 = aX0 + 16*XP;
    const uint32_t aR0 = sm32 + R_OFF + (mw*32 + (lane&15))*RP + (lane>>4)*16;
    const uint32_t aR1 = aR0 + 16*RP;
    // B staging lane constants (swizzled 64B-pitch)
    const uint32_t bRB  = (uint32_t)(nw*16 + (lane&7))*64;
    const uint32_t t_sw = (uint32_t)((lane&7) >> 1);
    const uint32_t b8   = (uint32_t)((lane>>3) & 1);
    const uint32_t swk0 = ((b8 ^ t_sw) & 3)*16;
    const uint32_t swk1 = (((2u + b8) ^ t_sw) & 3)*16;

    // ---------------- Phase A: x -> split bf16 in X region -----------------
    #pragma unroll
    for (int p = 0; p < 8; p++){
        int idx = tid + p*NT;
        int r = idx >> 6, c4 = idx & 63;
        float4 v = *(const float4*)(x + (size_t)(rowbase + r)*Dq + c4*4);
        __nv_bfloat16 h0,l0,h1,l1,h2,l2,h3,l3;
        split_bf(v.x,h0,l0); split_bf(v.y,h1,l1); split_bf(v.z,h2,l2); split_bf(v.w,h3,l3);
        *(uint2*)(sm + X_OFF + r*XP + c4*8)       = make_uint2(pk2(h0,h1), pk2(h2,h3));
        *(uint2*)(sm + X_OFF + r*XP + XLO + c4*8) = make_uint2(pk2(l0,l1), pk2(l2,l3));
    }
    __syncthreads();

    // ---------------- Phase B: logits = x @ memory^T (pipelined) -----------
    for (int nc = 0; nc < 4; nc++){
        float acc[2][2][4] = {};
        stage2(ST0, g_memB_h, g_memB_l, nc*128, Dq, 0); CP_COMMIT();
        #pragma unroll 1
        for (int kc = 0; kc < 8; kc++){
            if (kc < 7){
                stage2(((kc+1)&1)?ST1:ST0, g_memB_h, g_memB_l, nc*128, Dq, (kc+1)*32);
                CP_COMMIT();
                cp_wait<1>();
            } else cp_wait<0>();
            __syncthreads();
            gemm_split(acc, aX0 + kc*64, aX1 + kc*64, XLO, (kc&1)?ST1:ST0, bRB, swk0, swk1);
            __syncthreads();
        }
        #pragma unroll
        for (int mt = 0; mt < 2; mt++)
            #pragma unroll
            for (int nb = 0; nb < 2; nb++){
                int r = mw*32 + mt*16 + (lane>>2);
                int c = nc*128 + nw*16 + nb*8 + 2*(lane&3);
                *(float2*)(sm + R_OFF + r*RP + c*4)     = make_float2(acc[mt][nb][0], acc[mt][nb][1]);
                *(float2*)(sm + R_OFF + (r+8)*RP + c*4) = make_float2(acc[mt][nb][2], acc[mt][nb][3]);
            }
    }
    __syncthreads();

    // ---------------- Phase C: softmax + out_w + in-place split ------------
    for (int t4 = 0; t4 < 4; t4++){
        int r = wid*4 + t4;
        char* rbase = sm + R_OFF + r*RP;
        float v[16];
        #pragma unroll
        for (int j = 0; j < 8; j++){
            float2 p = *(float2*)(rbase + (2*lane + 64*j)*4);
            v[2*j] = p.x; v[2*j+1] = p.y;
        }
        float mx = v[0];
        #pragma unroll
        for (int i = 1; i < 16; i++) mx = fmaxf(mx, v[i]);
        #pragma unroll
        for (int o = 16; o > 0; o >>= 1) mx = fmaxf(mx, __shfl_xor_sync(~0u, mx, o));
        float s = 0.f;
        #pragma unroll
        for (int i = 0; i < 16; i++){ v[i] = __expf(v[i] - mx); s += v[i]; }
        #pragma unroll
        for (int o = 16; o > 0; o >>= 1) s += __shfl_xor_sync(~0u, s, o);
        float inv = 1.f / s;
        float* wout = out_w + (size_t)(rowbase + r)*Mq;
        #pragma unroll
        for (int j = 0; j < 8; j++){
            float w0 = v[2*j]*inv, w1 = v[2*j+1]*inv;
            v[2*j] = w0; v[2*j+1] = w1;
            *(float2*)(wout + 2*lane + 64*j) = make_float2(w0, w1);
        }
        __syncwarp();
        #pragma unroll
        for (int j = 0; j < 8; j++){
            __nv_bfloat16 h0,l0,h1,l1;
            split_bf(v[2*j], h0, l0); split_bf(v[2*j+1], h1, l1);
            int c = 2*lane + 64*j;
            *(uint32_t*)(rbase + 2*c)       = pk2(h0, h1);
            *(uint32_t*)(rbase + RLO + 2*c) = pk2(l0, l1);
        }
    }
    __syncthreads();

    // ---------------- Phase D: mr = w @ memory (pipelined) -----------------
    float dacc[2][2][2][4] = {};
    for (int nc = 0; nc < 2; nc++){
        stage2(ST0, g_memT_h, g_memT_l, nc*128, Mq, 0); CP_COMMIT();
        #pragma unroll 1
        for (int kc = 0; kc < 16; kc++){
            if (kc < 15){
                stage2(((kc+1)&1)?ST1:ST0, g_memT_h, g_memT_l, nc*128, Mq, (kc+1)*32);
                CP_COMMIT();
                cp_wait<1>();
            } else cp_wait<0>();
            __syncthreads();
            gemm_split(dacc[nc], aR0 + kc*64, aR1 + kc*64, RLO, (kc&1)?ST1:ST0, bRB, swk0, swk1);
            __syncthreads();
        }
    }
    // store mr split into R region (w fully consumed now)
    #pragma unroll
    for (int nc = 0; nc < 2; nc++)
        #pragma unroll
        for (int mt = 0; mt < 2; mt++)
            #pragma unroll
            for (int nb = 0; nb < 2; nb++){
                int r = mw*32 + mt*16 + (lane>>2);
                int c = nc*128 + nw*16 + nb*8 + 2*(lane&3);
                __nv_bfloat16 h0,l0,h1,l1;
                split_bf(dacc[nc][mt][nb][0], h0, l0); split_bf(dacc[nc][mt][nb][1], h1, l1);
                *(uint32_t*)(sm + R_OFF + r*RP + 2*c)       = pk2(h0,h1);
                *(uint32_t*)(sm + R_OFF + r*RP + RLO + 2*c) = pk2(l0,l1);
                split_bf(dacc[nc][mt][nb][2], h0, l0); split_bf(dacc[nc][mt][nb][3], h1, l1);
                *(uint32_t*)(sm + R_OFF + (r+8)*RP + 2*c)       = pk2(h0,h1);
                *(uint32_t*)(sm + R_OFF + (r+8)*RP + RLO + 2*c) = pk2(l0,l1);
            }
    __syncthreads();

    // ---------------- Phase E: gate = [x ; mr] @ Wg^T (hi-only), epilogue --
    for (int nc = 0; nc < 2; nc++){
        float gacc[2][2][4] = {};
        stage1(ST0, g_wg_h, nc*128, Mq, 0); CP_COMMIT();
        #pragma unroll 1
        for (int kc = 0; kc < 16; kc++){
            if (kc < 15){
                stage1(((kc+1)&1)?ST1:ST0, g_wg_h, nc*128, Mq, (kc+1)*32);
                CP_COMMIT();
                cp_wait<1>();
            } else cp_wait<0>();
            __syncthreads();
            uint32_t a0 = (kc < 8) ? (aX0 + kc*64) : (aR0 + (kc-8)*64);
            uint32_t a1 = (kc < 8) ? (aX1 + kc*64) : (aR1 + (kc-8)*64);
            gemm_hi(gacc, a0, a1, (kc&1)?ST1:ST0, bRB, swk0, swk1);
            __syncthreads();
        }
        // epilogue: enhanced = x + sigmoid(z + bg) * mr
        #pragma unroll
        for (int mt = 0; mt < 2; mt++)
            #pragma unroll
            for (int nb = 0; nb < 2; nb++){
                int e = nc*128 + nw*16 + nb*8 + 2*(lane&3);
                float b0 = __ldg(bg + e), b1 = __ldg(bg + e + 1);
                #pragma unroll
                for (int rh = 0; rh < 2; rh++){
                    int r = mw*32 + mt*16 + (lane>>2) + rh*8;
                    float z0 = gacc[mt][nb][rh*2]   + b0;
                    float z1 = gacc[mt][nb][rh*2+1] + b1;
                    uint32_t xh = *(uint32_t*)(sm + X_OFF + r*XP + 2*e);
                    uint32_t xl = *(uint32_t*)(sm + X_OFF + r*XP + XLO + 2*e);
                    uint32_t mh = *(uint32_t*)(sm + R_OFF + r*RP + 2*e);
                    uint32_t ml = *(uint32_t*)(sm + R_OFF + r*RP + RLO + 2*e);
                    float x0 = bf2sum(xh, xl, 0), x1 = bf2sum(xh, xl, 1);
                    float m0 = bf2sum(mh, ml, 0), m1 = bf2sum(mh, ml, 1);
                    float g0 = 1.f/(1.f + __expf(-z0));
                    float g1 = 1.f/(1.f + __expf(-z1));
                    *(float2*)(out_enh + (size_t)(rowbase + r)*Dq + e) =
                        make_float2(x0 + g0*m0, x1 + g1*m1);
                }
            }
    }
}

extern "C" void kernel_launch(void* const* d_in, const int* in_sizes, int n_in,
                              void* d_out, int out_size)
{
    const float* x    = (const float*)d_in[0];
    const float* memv = (const float*)d_in[1];
    const float* wg   = (const float*)d_in[2];
    const float* bg   = (const float*)d_in[3];

    float* out_enh = (float*)d_out;
    float* out_w   = out_enh + (size_t)NROWS * Dq;

    cudaFuncSetAttribute(vm_fused, cudaFuncAttributeMaxDynamicSharedMemorySize, SMEM_BYTES);

    vm_prep<<<(Mq*Dq + 511)/512, 512>>>(memv, wg);
    vm_fused<<<NROWS/RB, NT, SMEM_BYTES>>>(x, bg, out_enh, out_w);
}

// round 13
// speedup vs baseline: 2.3745x; 1.0487x over previous
#include <cuda_runtime.h>
#include <cuda_bf16.h>
#include <stdint.h>
#include <math.h>

#define Dq 256
#define Mq 512
#define RB 64
#define NT 512
#define NROWS (32*4096)

// ---- SMEM layout ----
#define R_OFF  0
#define RP     2064
#define RLO    1040
#define X_OFF  132096
#define XP     1040
#define XLO    528
// Staging: 2 buffers x 16KB. k32 phases: hi @ +0, lo @ +8192 (64B pitch, chunk-XOR swizzle).
// k64 phase E: hi-only, 128B pitch, row-XOR swizzle.
#define ST_OFF 198656
#define SMEM_BYTES 231424

__device__ __align__(16) __nv_bfloat16 g_memB_h[Mq*Dq], g_memB_l[Mq*Dq]; // [m][k]
__device__ __align__(16) __nv_bfloat16 g_memT_h[Dq*Mq], g_memT_l[Dq*Mq]; // [d][m]
__device__ __align__(16) __nv_bfloat16 g_wg_h[Dq*Mq],   g_wg_l[Dq*Mq];   // [e][dc]

__device__ __forceinline__ uint32_t smem_u32(const void* p){
    uint32_t a;
    asm("{ .reg .u64 t; cvta.to.shared.u64 t, %1; cvt.u32.u64 %0, t; }" : "=r"(a) : "l"(p));
    return a;
}
__device__ __forceinline__ void split_bf(float v, __nv_bfloat16& h, __nv_bfloat16& l){
    h = __float2bfloat16(v);
    l = __float2bfloat16(v - __bfloat162float(h));
}
__device__ __forceinline__ uint32_t pk2(__nv_bfloat16 a, __nv_bfloat16 b){
    uint16_t ua = *(uint16_t*)&a, ub = *(uint16_t*)&b;
    return (uint32_t)ua | ((uint32_t)ub << 16);
}
__device__ __forceinline__ float bf2sum(uint32_t h, uint32_t l, int hi){
    uint16_t uh = hi ? (uint16_t)(h >> 16) : (uint16_t)h;
    uint16_t ul = hi ? (uint16_t)(l >> 16) : (uint16_t)l;
    __nv_bfloat16 bh = *(__nv_bfloat16*)&uh, bl = *(__nv_bfloat16*)&ul;
    return __bfloat162float(bh) + __bfloat162float(bl);
}
__device__ __forceinline__ void ldsm4(unsigned* a, uint32_t addr){
    asm volatile("ldmatrix.sync.aligned.m8n8.x4.shared.b16 {%0,%1,%2,%3}, [%4];"
        : "=r"(a[0]), "=r"(a[1]), "=r"(a[2]), "=r"(a[3]) : "r"(addr));
}
__device__ __forceinline__ void ldsm2(unsigned* b, uint32_t addr){
    asm volatile("ldmatrix.sync.aligned.m8n8.x2.shared.b16 {%0,%1}, [%2];"
        : "=r"(b[0]), "=r"(b[1]) : "r"(addr));
}
__device__ __forceinline__ void mma(float* d, const unsigned* a, const unsigned* b){
    asm volatile("mma.sync.aligned.m16n8k16.row.col.f32.bf16.bf16.f32 "
        "{%0,%1,%2,%3}, {%4,%5,%6,%7}, {%8,%9}, {%0,%1,%2,%3};"
        : "+f"(d[0]), "+f"(d[1]), "+f"(d[2]), "+f"(d[3])
        : "r"(a[0]), "r"(a[1]), "r"(a[2]), "r"(a[3]), "r"(b[0]), "r"(b[1]));
}
__device__ __forceinline__ void cpa16(uint32_t s, const void* g){
    asm volatile("cp.async.cg.shared.global [%0], [%1], 16;" :: "r"(s), "l"(g));
}
#define CP_COMMIT() asm volatile("cp.async.commit_group;" ::: "memory")
template<int N> __device__ __forceinline__ void cp_wait(){
    asm volatile("cp.async.wait_group %0;" :: "n"(N) : "memory");
}

// stage [128 rows][32 k] hi+lo into swizzled 64B-pitch buffer
__device__ __forceinline__ void stage2(uint32_t st, const __nv_bfloat16* gh,
        const __nv_bfloat16* gl, int row0, int gs, int col0){
    int idx = threadIdx.x;
    int row = idx >> 2, c = idx & 3;
    uint32_t sa = st + row*64 + ((c ^ ((row>>1)&3)) & 3)*16;
    size_t go = (size_t)(row0 + row)*gs + col0 + c*8;
    cpa16(sa, gh + go);
    cpa16(sa + 8192, gl + go);
}
// stage [128 rows][64 k] hi-only into 128B-pitch row-XOR swizzled buffer
__device__ __forceinline__ void stage1_64(uint32_t st, const __nv_bfloat16* gh,
        int row0, int gs, int col0){
    #pragma unroll
    for (int p = 0; p < 2; p++){
        int idx = threadIdx.x + p*NT;        // 0..1023
        int row = idx >> 3, c = idx & 7;
        uint32_t sa = st + row*128 + ((c ^ (row & 7)) & 7)*16;
        cpa16(sa, gh + (size_t)(row0 + row)*gs + col0 + c*8);
    }
}

// split GEMM chunk: A m32 x B n16 x k32, 3-term split => 24 mma
__device__ __forceinline__ void gemm_split(float acc[2][2][4], uint32_t a0, uint32_t a1,
        uint32_t alo, uint32_t st, uint32_t bRB, uint32_t swk0, uint32_t swk1){
    #pragma unroll
    for (int ki = 0; ki < 2; ki++){
        unsigned ah0[4], al0[4], ah1[4], al1[4];
        ldsm4(ah0, a0 + ki*32); ldsm4(al0, a0 + alo + ki*32);
        ldsm4(ah1, a1 + ki*32); ldsm4(al1, a1 + alo + ki*32);
        uint32_t sw = ki ? swk1 : swk0;
        #pragma unroll
        for (int nb = 0; nb < 2; nb++){
            unsigned bh[2], bl[2];
            uint32_t ba = st + bRB + nb*512 + sw;
            ldsm2(bh, ba); ldsm2(bl, ba + 8192);
            mma(acc[0][nb], ah0, bh); mma(acc[1][nb], ah1, bh);
            mma(acc[0][nb], ah0, bl); mma(acc[1][nb], ah1, bl);
            mma(acc[0][nb], al0, bh); mma(acc[1][nb], al1, bh);
        }
    }
}
// hi-only GEMM chunk, k64 staging (128B pitch, row-XOR swizzle): 16 mma
__device__ __forceinline__ void gemm_hi64(float acc[2][2][4], uint32_t a0, uint32_t a1,
        uint32_t st, uint32_t rowB, uint32_t l7, uint32_t b8){
    #pragma unroll
    for (int ki = 0; ki < 4; ki++){
        unsigned ah0[4], ah1[4];
        ldsm4(ah0, a0 + ki*32); ldsm4(ah1, a1 + ki*32);
        #pragma unroll
        for (int nb = 0; nb < 2; nb++){
            unsigned bh[2];
            uint32_t chunk = 2u*ki + b8;
            uint32_t ba = st + rowB + nb*1024 + ((chunk ^ l7) & 7)*16;
            ldsm2(bh, ba);
            mma(acc[0][nb], ah0, bh); mma(acc[1][nb], ah1, bh);
        }
    }
}

__global__ void vm_prep(const float* __restrict__ mem, const float* __restrict__ wg){
    int idx = blockIdx.x*blockDim.x + threadIdx.x;
    if (idx < Mq*Dq){
        int m = idx >> 8, k = idx & 255;
        __nv_bfloat16 h, l;
        split_bf(mem[idx], h, l);
        g_memB_h[idx] = h;          g_memB_l[idx] = l;
        g_memT_h[k*Mq + m] = h;     g_memT_l[k*Mq + m] = l;
        split_bf(wg[idx], h, l);
        g_wg_h[idx] = h;            g_wg_l[idx] = l;
    }
}

__global__ __launch_bounds__(NT, 1)
void vm_fused(const float* __restrict__ x,
              const float* __restrict__ bg,
              float* __restrict__ out_enh,
              float* __restrict__ out_w)
{
    extern __shared__ char sm[];
    const uint32_t sm32 = smem_u32(sm);
    const uint32_t ST0 = sm32 + ST_OFF, ST1 = ST0 + 16384;

    const int tid = threadIdx.x;
    const int wid = tid >> 5, lane = tid & 31;
    const int mw = wid & 1, nw = wid >> 1;          // warp grid 2(m) x 8(n)
    const int rowbase = blockIdx.x * RB;

    const uint32_t aX0 = sm32 + X_OFF + (mw*32 + (lane&15))*XP + (lane>>4)*16;
    const uint32_t aX1 = aX0 + 16*XP;
    const uint32_t aR0 = sm32 + R_OFF + (mw*32 + (lane&15))*RP + (lane>>4)*16;
    const uint32_t aR1 = aR0 + 16*RP;
    // k32 staging lane constants
    const uint32_t bRB  = (uint32_t)(nw*16 + (lane&7))*64;
    const uint32_t t_sw = (uint32_t)((lane&7) >> 1);
    const uint32_t b8   = (uint32_t)((lane>>3) & 1);
    const uint32_t swk0 = ((b8 ^ t_sw) & 3)*16;
    const uint32_t swk1 = (((2u + b8) ^ t_sw) & 3)*16;
    // k64 staging lane constants (phase E)
    const uint32_t rowB64 = (uint32_t)(nw*16 + (lane&7))*128;
    const uint32_t l7 = (uint32_t)(lane & 7);

    // ---------------- Phase A: x -> split bf16 in X region -----------------
    #pragma unroll
    for (int p = 0; p < 8; p++){
        int idx = tid + p*NT;
        int r = idx >> 6, c4 = idx & 63;
        float4 v = *(const float4*)(x + (size_t)(rowbase + r)*Dq + c4*4);
        __nv_bfloat16 h0,l0,h1,l1,h2,l2,h3,l3;
        split_bf(v.x,h0,l0); split_bf(v.y,h1,l1); split_bf(v.z,h2,l2); split_bf(v.w,h3,l3);
        *(uint2*)(sm + X_OFF + r*XP + c4*8)       = make_uint2(pk2(h0,h1), pk2(h2,h3));
        *(uint2*)(sm + X_OFF + r*XP + XLO + c4*8) = make_uint2(pk2(l0,l1), pk2(l2,l3));
    }

    // ---------------- Phase B: logits = x @ memory^T (1 sync/chunk) --------
    for (int nc = 0; nc < 4; nc++){
        float acc[2][2][4] = {};
        stage2(ST0, g_memB_h, g_memB_l, nc*128, Dq, 0); CP_COMMIT();
        #pragma unroll 1
        for (int kc = 0; kc < 8; kc++){
            cp_wait<0>();
            __syncthreads();
            if (kc < 7){
                stage2(((kc+1)&1)?ST1:ST0, g_memB_h, g_memB_l, nc*128, Dq, (kc+1)*32);
                CP_COMMIT();
            }
            gemm_split(acc, aX0 + kc*64, aX1 + kc*64, XLO, (kc&1)?ST1:ST0, bRB, swk0, swk1);
        }
        #pragma unroll
        for (int mt = 0; mt < 2; mt++)
            #pragma unroll
            for (int nb = 0; nb < 2; nb++){
                int r = mw*32 + mt*16 + (lane>>2);
                int c = nc*128 + nw*16 + nb*8 + 2*(lane&3);
                *(float2*)(sm + R_OFF + r*RP + c*4)     = make_float2(acc[mt][nb][0], acc[mt][nb][1]);
                *(float2*)(sm + R_OFF + (r+8)*RP + c*4) = make_float2(acc[mt][nb][2], acc[mt][nb][3]);
            }
    }
    __syncthreads();

    // ---------------- Phase C: softmax + out_w + in-place split ------------
    for (int t4 = 0; t4 < 4; t4++){
        int r = wid*4 + t4;
        char* rbase = sm + R_OFF + r*RP;
        float v[16];
        #pragma unroll
        for (int j = 0; j < 8; j++){
            float2 p = *(float2*)(rbase + (2*lane + 64*j)*4);
            v[2*j] = p.x; v[2*j+1] = p.y;
        }
        float mx = v[0];
        #pragma unroll
        for (int i = 1; i < 16; i++) mx = fmaxf(mx, v[i]);
        #pragma unroll
        for (int o = 16; o > 0; o >>= 1) mx = fmaxf(mx, __shfl_xor_sync(~0u, mx, o));
        float s = 0.f;
        #pragma unroll
        for (int i = 0; i < 16; i++){ v[i] = __expf(v[i] - mx); s += v[i]; }
        #pragma unroll
        for (int o = 16; o > 0; o >>= 1) s += __shfl_xor_sync(~0u, s, o);
        float inv = 1.f / s;
        float* wout = out_w + (size_t)(rowbase + r)*Mq;
        #pragma unroll
        for (int j = 0; j < 8; j++){
            float w0 = v[2*j]*inv, w1 = v[2*j+1]*inv;
            v[2*j] = w0; v[2*j+1] = w1;
            *(float2*)(wout + 2*lane + 64*j) = make_float2(w0, w1);
        }
        __syncwarp();
        #pragma unroll
        for (int j = 0; j < 8; j++){
            __nv_bfloat16 h0,l0,h1,l1;
            split_bf(v[2*j], h0, l0); split_bf(v[2*j+1], h1, l1);
            int c = 2*lane + 64*j;
            *(uint32_t*)(rbase + 2*c)       = pk2(h0, h1);
            *(uint32_t*)(rbase + RLO + 2*c) = pk2(l0, l1);
        }
    }
    __syncthreads();

    // ---------------- Phase D: mr = w @ memory (1 sync/chunk) --------------
    float dacc[2][2][2][4] = {};
    for (int nc = 0; nc < 2; nc++){
        stage2(ST0, g_memT_h, g_memT_l, nc*128, Mq, 0); CP_COMMIT();
        #pragma unroll 1
        for (int kc = 0; kc < 16; kc++){
            cp_wait<0>();
            __syncthreads();
            if (kc < 15){
                stage2(((kc+1)&1)?ST1:ST0, g_memT_h, g_memT_l, nc*128, Mq, (kc+1)*32);
                CP_COMMIT();
            }
            gemm_split(dacc[nc], aR0 + kc*64, aR1 + kc*64, RLO, (kc&1)?ST1:ST0, bRB, swk0, swk1);
        }
    }
    __syncthreads();   // all reads of w from R done before overwriting with mr
    #pragma unroll
    for (int nc = 0; nc < 2; nc++)
        #pragma unroll
        for (int mt = 0; mt < 2; mt++)
            #pragma unroll
            for (int nb = 0; nb < 2; nb++){
                int r = mw*32 + mt*16 + (lane>>2);
                int c = nc*128 + nw*16 + nb*8 + 2*(lane&3);
                __nv_bfloat16 h0,l0,h1,l1;
                split_bf(dacc[nc][mt][nb][0], h0, l0); split_bf(dacc[nc][mt][nb][1], h1, l1);
                *(uint32_t*)(sm + R_OFF + r*RP + 2*c)       = pk2(h0,h1);
                *(uint32_t*)(sm + R_OFF + r*RP + RLO + 2*c) = pk2(l0,l1);
                split_bf(dacc[nc][mt][nb][2], h0, l0); split_bf(dacc[nc][mt][nb][3], h1, l1);
                *(uint32_t*)(sm + R_OFF + (r+8)*RP + 2*c)       = pk2(h0,h1);
                *(uint32_t*)(sm + R_OFF + (r+8)*RP + RLO + 2*c) = pk2(l0,l1);
            }
    __syncthreads();

    // ---------------- Phase E: gate = [x ; mr] @ Wg^T (hi-only, k64) -------
    for (int nc = 0; nc < 2; nc++){
        float gacc[2][2][4] = {};
        stage1_64(ST0, g_wg_h, nc*128, Mq, 0); CP_COMMIT();
        #pragma unroll 1
        for (int kc = 0; kc < 8; kc++){
            cp_wait<0>();
            __syncthreads();
            if (kc < 7){
                stage1_64(((kc+1)&1)?ST1:ST0, g_wg_h, nc*128, Mq, (kc+1)*64);
                CP_COMMIT();
            }
            uint32_t a0 = (kc < 4) ? (aX0 + kc*128) : (aR0 + (kc-4)*128);
            uint32_t a1 = (kc < 4) ? (aX1 + kc*128) : (aR1 + (kc-4)*128);
            gemm_hi64(gacc, a0, a1, (kc&1)?ST1:ST0, rowB64, l7, b8);
        }
        // epilogue: enhanced = x + sigmoid(z + bg) * mr
        #pragma unroll
        for (int mt = 0; mt < 2; mt++)
            #pragma unroll
            for (int nb = 0; nb < 2; nb++){
                int e = nc*128 + nw*16 + nb*8 + 2*(lane&3);
                float b0 = __ldg(bg + e), b1 = __ldg(bg + e + 1);
                #pragma unroll
                for (int rh = 0; rh < 2; rh++){
                    int r = mw*32 + mt*16 + (lane>>2) + rh*8;
                    float z0 = gacc[mt][nb][rh*2]   + b0;
                    float z1 = gacc[mt][nb][rh*2+1] + b1;
                    uint32_t xh = *(uint32_t*)(sm + X_OFF + r*XP + 2*e);
                    uint32_t xl = *(uint32_t*)(sm + X_OFF + r*XP + XLO + 2*e);
                    uint32_t mh = *(uint32_t*)(sm + R_OFF + r*RP + 2*e);
                    uint32_t ml = *(uint32_t*)(sm + R_OFF + r*RP + RLO + 2*e);
                    float x0 = bf2sum(xh, xl, 0), x1 = bf2sum(xh, xl, 1);
                    float m0 = bf2sum(mh, ml, 0), m1 = bf2sum(mh, ml, 1);
                    float g0 = 1.f/(1.f + __expf(-z0));
                    float g1 = 1.f/(1.f + __expf(-z1));
                    *(float2*)(out_enh + (size_t)(rowbase + r)*Dq + e) =
                        make_float2(x0 + g0*m0, x1 + g1*m1);
                }
            }
    }
}

extern "C" void kernel_launch(void* const* d_in, const int* in_sizes, int n_in,
                              void* d_out, int out_size)
{
    const float* x    = (const float*)d_in[0];
    const float* memv = (const float*)d_in[1];
    const float* wg   = (const float*)d_in[2];
    const float* bg   = (const float*)d_in[3];

    float* out_enh = (float*)d_out;
    float* out_w   = out_enh + (size_t)NROWS * Dq;

    cudaFuncSetAttribute(vm_fused, cudaFuncAttributeMaxDynamicSharedMemorySize, SMEM_BYTES);

    vm_prep<<<(Mq*Dq + 511)/512, 512>>>(memv, wg);
    vm_fused<<<NROWS/RB, NT, SMEM_BYTES>>>(x, bg, out_enh, out_w);
}